// round 12
// baseline (speedup 1.0000x reference)
#include <cuda_runtime.h>
#include <cuda_bf16.h>
#include <math.h>

#define BB   8
#define CCH  64
#define HH   192
#define WWD  192
#define HWW  (HH*WWD)
#define NCLS 2
#define NSP  8

typedef unsigned long long u64;

// packed f32x2 helpers
#define FMA2(acc, a, b)   asm("fma.rn.f32x2 %0, %1, %2, %0;" : "+l"(acc) : "l"(a), "l"(b))
#define PACK2(d, lo, hi)  asm("mov.b64 %0, {%1, %2};" : "=l"(d) : "f"(lo), "f"(hi))
#define UNPK(lo, hi, d)   asm("mov.b64 {%0, %1}, %2;" : "=f"(lo), "=f"(hi) : "l"(d))

// cp.async helpers
__device__ __forceinline__ unsigned sm_addr(const void* p){
    unsigned a; asm("{ .reg .u64 t; cvta.to.shared.u64 t, %1; cvt.u32.u64 %0, t; }" : "=r"(a) : "l"(p));
    return a;
}
__device__ __forceinline__ void cp_async16(void* smem_dst, const void* gmem_src){
    asm volatile("cp.async.cg.shared.global [%0], [%1], 16;" :: "r"(sm_addr(smem_dst)), "l"(gmem_src) : "memory");
}
#define CP_COMMIT() asm volatile("cp.async.commit_group;" ::: "memory")
#define CP_WAIT0()  asm volatile("cp.async.wait_group 0;" ::: "memory")

// ---------------- scratch (device globals; zero at module load) ----------------
__device__ __nv_bfloat16 g_sP[BB*16*194*200];
__device__ __nv_bfloat16 g_sQ[BB*16*194*200];
__device__ __nv_bfloat16 g_xbf[(size_t)BB*CCH*HWW];  // x pre-converted to bf16
__device__ float g_A[BB*NCLS*HWW];           // [b][c][hw]
__device__ float g_R[BB*16*9*64];            // [b][sc][delta][e]
__device__ float g_S[BB*NCLS*NSP];           // per-map sums (of bf16-rounded values)
__device__ float g_tok2[BB*NCLS*CCH];        // [b][c][d]
__device__ float g_U[BB*NCLS*CCH*9];         // [b][c][o][delta]
__device__ float g_bnsum[CCH];
__device__ float g_bnsumsq[CCH];

__device__ __forceinline__ float sigmoidf_(float x){ return 1.f/(1.f+__expf(-x)); }

// ---------------- kernel 0: x -> bf16  (+ folded accumulator init) ----------------
__global__ void xconv_kernel(const float* __restrict__ x){
    if (blockIdx.x < 290){
        int i = blockIdx.x*256 + threadIdx.x;
        if (i < BB*16*9*64) g_R[i] = 0.f;
        if (i < BB*NCLS*NSP) g_S[i] = 0.f;
        if (i < BB*NCLS*CCH) g_tok2[i] = 0.f;
        if (i < CCH){ g_bnsum[i] = 0.f; g_bnsumsq[i] = 0.f; }
    }
    size_t i = ((size_t)blockIdx.x*256 + threadIdx.x)*8;
    float4 v0 = *(const float4*)&x[i];
    float4 v1 = *(const float4*)&x[i+4];
    __nv_bfloat162 p0 = __floats2bfloat162_rn(v0.x, v0.y);
    __nv_bfloat162 p1 = __floats2bfloat162_rn(v0.z, v0.w);
    __nv_bfloat162 p2 = __floats2bfloat162_rn(v1.x, v1.y);
    __nv_bfloat162 p3 = __floats2bfloat162_rn(v1.z, v1.w);
    uint4 o;
    o.x = *(unsigned*)&p0; o.y = *(unsigned*)&p1; o.z = *(unsigned*)&p2; o.w = *(unsigned*)&p3;
    *(uint4*)&g_xbf[i] = o;
}

// ---------------- kernel 1: space maps (P/Q padded layouts) + sums + attention A ----------------
__global__ void space_kernel(const float* __restrict__ cs, const float* __restrict__ Wc,
                             const float* __restrict__ Wcv, const float* __restrict__ Wattn,
                             const float* __restrict__ Wcomb){
    int h  = blockIdx.x;      // 0..191
    int bc = blockIdx.y;      // 0..15
    __shared__ float cp3[3*194];
    __shared__ float ssum[NSP];
    int t = threadIdx.x;      // 192
    if (t < NSP) ssum[t] = 0.f;
    const float* csp = cs + (size_t)bc*HWW;
    for (int idx = t; idx < 3*194; idx += 192){
        int r  = idx / 194;
        int wi = idx - r*194;
        int hh = h - 1 + r, ww = wi - 1;
        float v = 0.f;
        if (hh >= 0 && hh < HH && ww >= 0 && ww < WWD) v = sigmoidf_(csp[hh*WWD + ww]);
        cp3[idx] = v;
    }
    __syncthreads();
    int w = t;
    float cp = cp3[194 + w + 1];
    {   // attention map (full precision)
        float a = 0.f;
        #pragma unroll
        for (int s = 0; s < 8; s++) a += Wcomb[s]*Wcv[s]*sigmoidf_(cp*Wattn[s]);
        g_A[(size_t)bc*HWW + h*WWD + w] = a;
    }
    float sv[8];
    sv[0] = cp;
    #pragma unroll
    for (int os = 0; os < 7; os++){
        float acc = 0.f;
        #pragma unroll
        for (int r = 0; r < 3; r++)
            #pragma unroll
            for (int c = 0; c < 3; c++)
                acc += Wc[os*9 + r*3 + c] * cp3[r*194 + w + c];
        sv[os+1] = sigmoidf_(acc);
    }
    int gr = h + 1;   // padded row index
    #pragma unroll
    for (int s = 0; s < 8; s++){
        __nv_bfloat16 bv = __float2bfloat16(sv[s]);
        size_t rowbase = ((size_t)(bc*8 + s)*194 + gr)*200;
        g_sP[rowbase + w + 1] = bv;
        g_sQ[rowbase + w]     = bv;
        float v = __bfloat162float(bv);
        #pragma unroll
        for (int off = 16; off > 0; off >>= 1) v += __shfl_down_sync(0xffffffffu, v, off);
        if ((t & 31) == 0) atomicAdd(&ssum[s], v);
    }
    __syncthreads();
    if (t < NSP) atomicAdd(&g_S[bc*NSP + t], ssum[t]);
}

// ---------------- kernel 2: correlation GEMM, bf16 m16n8k16, warp tile m32 x n48 ----------------
#define RW 6
#define CTHR 192
#define SROW_W 100      // u32 words per staged space row
#define SC_STRIDE 400   // 4 slots * SROW_W
#define SQ_OFF 6400     // word offset of Q region
#define XS_BASE 12800   // word offset of x region (2 slots * 6400)
#define XROW_W 100

__device__ __forceinline__ void stage_space_row(unsigned* sm, int b, int gr, int t){
    int slot = gr & 3;
    for (int idx = t; idx < 800; idx += CTHR){
        int j  = idx >> 1;           // 0..399
        int sc = j / 25;
        int w16 = j - sc*25;
        const __nv_bfloat16* srcA = (idx & 1) ? g_sQ : g_sP;
        unsigned* dstbase = sm + ((idx & 1) ? SQ_OFF : 0);
        const char* s = (const char*)(srcA + ((size_t)(b*16 + sc)*194 + gr)*200) + w16*16;
        unsigned* d = dstbase + sc*SC_STRIDE + slot*SROW_W + w16*4;
        cp_async16(d, s);
    }
}

__device__ __forceinline__ void stage_x_row(unsigned* sm, int b, int h, int t){
    int xslot = h & 1;
    for (int idx = t; idx < 1536; idx += CTHR){
        int e = idx / 24;
        int o = idx - e*24;
        const char* s = (const char*)(g_xbf + ((size_t)(b*64 + e))*HWW + h*WWD) + o*16;
        unsigned* d = sm + XS_BASE + xslot*6400 + e*XROW_W + o*4;
        cp_async16(d, s);
    }
}

__global__ void corr_tc_kernel(){
    extern __shared__ unsigned sm32[];
    int b  = blockIdx.y;
    int h0 = blockIdx.x * RW;
    int t  = threadIdx.x;      // 192
    int warp = t >> 5, lane = t & 31;
    int lk = lane & 3, le = lane >> 2;
    int mt2 = warp & 1;        // m-strip: rows mt2*32 .. +31
    int ng  = warp >> 1;       // 0..2, n-tiles ng*6 .. +5

    int baseoff[6], kyv[6];
    #pragma unroll
    for (int nt = 0; nt < 6; nt++){
        int n = (ng*6 + nt)*8 + le;
        int sc = n / 9, di = n - sc*9;
        int ky = di/3, kx = di - ky*3;
        int sh = 2 - kx;
        int par = sh & 1;
        baseoff[nt] = (par ? SQ_OFF : 0) + sc*SC_STRIDE + ((sh - par) >> 1) + lk;
        kyv[nt] = ky;
    }
    float acc[12][4];
    #pragma unroll
    for (int j = 0; j < 12; j++){ acc[j][0]=0.f; acc[j][1]=0.f; acc[j][2]=0.f; acc[j][3]=0.f; }

    // prologue: space rows gr=h0..h0+2 (habs h0-1..h0+1) + x row h0
    stage_space_row(sm32, b, h0,   t);
    stage_space_row(sm32, b, h0+1, t);
    stage_space_row(sm32, b, h0+2, t);
    stage_x_row(sm32, b, h0, t);
    CP_COMMIT();

    int xrow = mt2*32 + le;
    #pragma unroll 1
    for (int rr = 0; rr < RW; rr++){
        int h = h0 + rr;
        CP_WAIT0();
        __syncthreads();
        if (rr + 1 < RW){
            stage_space_row(sm32, b, h+3, t);
            stage_x_row(sm32, b, h+1, t);
            CP_COMMIT();
        }
        int xb = XS_BASE + (h & 1)*6400 + xrow*XROW_W + lk;
        int off[6];
        #pragma unroll
        for (int nt = 0; nt < 6; nt++) off[nt] = baseoff[nt] + ((h + 2 - kyv[nt]) & 3)*SROW_W;
        #pragma unroll
        for (int ks = 0; ks < 12; ks++){
            int kw = ks*8;
            unsigned a00 = sm32[xb + kw];
            unsigned a01 = sm32[xb + 8*XROW_W  + kw];
            unsigned a02 = sm32[xb + kw + 4];
            unsigned a03 = sm32[xb + 8*XROW_W  + kw + 4];
            unsigned a10 = sm32[xb + 16*XROW_W + kw];
            unsigned a11 = sm32[xb + 24*XROW_W + kw];
            unsigned a12 = sm32[xb + 16*XROW_W + kw + 4];
            unsigned a13 = sm32[xb + 24*XROW_W + kw + 4];
            #pragma unroll
            for (int nt = 0; nt < 6; nt++){
                unsigned b0 = sm32[off[nt] + kw];
                unsigned b1 = sm32[off[nt] + kw + 4];
                asm("mma.sync.aligned.m16n8k16.row.col.f32.bf16.bf16.f32 "
                    "{%0,%1,%2,%3}, {%4,%5,%6,%7}, {%8,%9}, {%0,%1,%2,%3};"
                    : "+f"(acc[nt][0]), "+f"(acc[nt][1]), "+f"(acc[nt][2]), "+f"(acc[nt][3])
                    : "r"(a00), "r"(a01), "r"(a02), "r"(a03), "r"(b0), "r"(b1));
                asm("mma.sync.aligned.m16n8k16.row.col.f32.bf16.bf16.f32 "
                    "{%0,%1,%2,%3}, {%4,%5,%6,%7}, {%8,%9}, {%0,%1,%2,%3};"
                    : "+f"(acc[6+nt][0]), "+f"(acc[6+nt][1]), "+f"(acc[6+nt][2]), "+f"(acc[6+nt][3])
                    : "r"(a10), "r"(a11), "r"(a12), "r"(a13), "r"(b0), "r"(b1));
            }
        }
        __syncthreads();
    }
    // epilogue
    #pragma unroll
    for (int i = 0; i < 2; i++){
        int e0 = mt2*32 + i*16 + le;
        #pragma unroll
        for (int nt = 0; nt < 6; nt++){
            int n0 = (ng*6 + nt)*8 + lk*2;
            int sc0 = n0 / 9,     di0 = n0 - sc0*9;
            int sc1 = (n0+1) / 9, di1 = (n0+1) - sc1*9;
            float* ac = acc[i*6 + nt];
            atomicAdd(&g_R[((size_t)(b*16 + sc0)*9 + di0)*64 + e0],     ac[0]);
            atomicAdd(&g_R[((size_t)(b*16 + sc1)*9 + di1)*64 + e0],     ac[1]);
            atomicAdd(&g_R[((size_t)(b*16 + sc0)*9 + di0)*64 + e0 + 8], ac[2]);
            atomicAdd(&g_R[((size_t)(b*16 + sc1)*9 + di1)*64 + e0 + 8], ac[3]);
        }
    }
}

// ---------------- kernel 3: tok2 v3 — 64 blocks = (s x dgroup8), R staged once ----------------
#define TPAD 580
__global__ void tok2_kernel(const float* __restrict__ Wx, const float* __restrict__ Wcs){
    __shared__ float wxs[8*TPAD];       // [dd][di*64+e], padded rows
    __shared__ float Rs[16*TPAD];       // [bc][di*64+e], padded rows
    int s  = blockIdx.x >> 3;
    int dg = blockIdx.x & 7;
    int t  = threadIdx.x;               // 256
    for (int idx = t; idx < 8*576; idx += 256){
        int dd = idx / 576, k = idx - dd*576;   // k = di*64+e
        int di = k >> 6, e = k & 63;
        wxs[dd*TPAD + k] = Wx[((size_t)(s*64 + dg*8 + dd))*576 + e*9 + di];
    }
    for (int idx = t; idx < 16*144; idx += 256){
        int bc = idx / 144, w4 = idx - bc*144;
        int bb = bc >> 1, c = bc & 1;
        ((float4*)&Rs[bc*TPAD])[w4] = ((const float4*)&g_R[((size_t)(bb*16 + c*8 + s))*576])[w4];
    }
    __syncthreads();
    int bc = t >> 4;
    int dq = t & 15;
    int dd = dq >> 1, half = dq & 1;
    const float4* wp = (const float4*)&wxs[dd*TPAD + half*288];
    const float4* rp = (const float4*)&Rs[bc*TPAD + half*288];
    float p = 0.f;
    #pragma unroll 8
    for (int k = 0; k < 72; k++){
        float4 a = wp[k], b4 = rp[k];
        p += a.x*b4.x + a.y*b4.y + a.z*b4.z + a.w*b4.w;
    }
    p += __shfl_xor_sync(0xffffffffu, p, 1);
    if (half == 0){
        float ws = Wcs[s] / g_S[bc*8 + s];
        atomicAdd(&g_tok2[bc*64 + dg*8 + dd], ws*p);
    }
}

// ---------------- kernel 5: U v2 — 16 blocks = o-groups of 4, coalesced Wsingle ----------------
__global__ void u_kernel(const float* __restrict__ Wsingle){
    int og = blockIdx.x;            // o0 = og*4
    int t  = threadIdx.x;           // 576
    __shared__ float tk[16*64];
    __shared__ float ws[36*65];     // [j = ol*9+di][d], padded
    if (t < 512){
        tk[t] = g_tok2[t];
        tk[t+512] = g_tok2[t+512];
    }
    for (int idx = t; idx < 2304; idx += 576){
        int ol = idx / 576, r = idx - ol*576;   // r = d*9+di
        int d = r / 9, di = r - d*9;
        ws[(ol*9 + di)*65 + d] = Wsingle[(size_t)og*2304 + idx];
    }
    __syncthreads();
    int bc = t / 36, j = t - bc*36;
    const float* wr = ws + j*65;
    const float* tr = tk + bc*64;
    float acc = 0.f;
    #pragma unroll
    for (int d = 0; d < 64; d++) acc += wr[d]*tr[d];
    int ol = j / 9, di = j - ol*9;
    g_U[(size_t)bc*576 + (og*4 + ol)*9 + di] = acc;
}

// ---------------- shared y-compute helpers ----------------
#define YROWS 4
#define AT_RS 196
__device__ __forceinline__ void stage_AU2(float* At, float* Us2, int b, int h0, int t){
    for (int idx = t; idx < 2*6*194; idx += 192){
        int ccv = idx / (6*194);
        int rem = idx - ccv*(6*194);
        int r   = rem / 194;
        int wi  = rem - r*194;
        int hh = h0 - 1 + r, ww = wi - 1;
        float v = 0.f;
        if (hh >= 0 && hh < HH && ww >= 0 && ww < WWD)
            v = g_A[((size_t)(b*2 + ccv))*HWW + hh*WWD + ww];
        At[ccv*(6*AT_RS) + r*AT_RS + wi] = v;
    }
    for (int idx = t; idx < 1152; idx += 192){
        float v = g_U[(size_t)b*1152 + idx];
        Us2[2*idx]   = v;
        Us2[2*idx+1] = v;
    }
}

__device__ __forceinline__ void load_ap(u64 ap[2][3][5], const float* At, int rr, int w0){
    #pragma unroll
    for (int ccv = 0; ccv < 2; ccv++){
        #pragma unroll
        for (int ky = 0; ky < 3; ky++){
            const float* arow = At + ccv*(6*AT_RS) + (rr + ky)*AT_RS + w0;
            float a0=arow[0], a1=arow[1], a2=arow[2], a3=arow[3], a4=arow[4], a5=arow[5];
            PACK2(ap[ccv][ky][0], a0, a1);
            PACK2(ap[ccv][ky][1], a1, a2);
            PACK2(ap[ccv][ky][2], a2, a3);
            PACK2(ap[ccv][ky][3], a3, a4);
            PACK2(ap[ccv][ky][4], a4, a5);
        }
    }
}

__device__ __forceinline__ void y_quad2(const u64 ap[2][3][5], const float* Us2, int o,
                                        float& o0, float& o1, float& o2, float& o3){
    u64 a01 = 0ull, a23 = 0ull;
    #pragma unroll
    for (int ccv = 0; ccv < 2; ccv++){
        const u64* up = (const u64*)Us2 + (ccv*64 + o)*9;
        #pragma unroll
        for (int ky = 0; ky < 3; ky++){
            u64 u0 = up[ky*3+0], u1 = up[ky*3+1], u2 = up[ky*3+2];
            FMA2(a01, u0, ap[ccv][ky][0]);
            FMA2(a01, u1, ap[ccv][ky][1]);
            FMA2(a01, u2, ap[ccv][ky][2]);
            FMA2(a23, u0, ap[ccv][ky][2]);
            FMA2(a23, u1, ap[ccv][ky][3]);
            FMA2(a23, u2, ap[ccv][ky][4]);
        }
    }
    UNPK(o0, o1, a01);
    UNPK(o2, o3, a23);
}

// ---------------- kernel 6: BN stats only ----------------
__global__ void y_kernel(){
    __shared__ float At[2*6*AT_RS];
    __shared__ float Us2[2304];
    __shared__ float bs[64], bsq[64];
    int b  = blockIdx.y;
    int h0 = blockIdx.x * YROWS;
    int t  = threadIdx.x;           // 192
    if (t < 64){ bs[t] = 0.f; bsq[t] = 0.f; }
    stage_AU2(At, Us2, b, h0, t);
    __syncthreads();

    int rr = t / 48, wq = t - rr*48;
    int w0 = wq * 4;
    u64 ap[2][3][5];
    load_ap(ap, At, rr, w0);
    for (int o = 0; o < 64; o++){
        float o0,o1,o2,o3;
        y_quad2(ap, Us2, o, o0, o1, o2, o3);
        float s1 = o0+o1+o2+o3;
        float s2 = o0*o0+o1*o1+o2*o2+o3*o3;
        #pragma unroll
        for (int off = 16; off > 0; off >>= 1){
            s1 += __shfl_down_sync(0xffffffffu, s1, off);
            s2 += __shfl_down_sync(0xffffffffu, s2, off);
        }
        if ((t & 31) == 0){ atomicAdd(&bs[o], s1); atomicAdd(&bsq[o], s2); }
    }
    __syncthreads();
    if (t < 64){ atomicAdd(&g_bnsum[t], bs[t]); atomicAdd(&g_bnsumsq[t], bsq[t]); }
}

// ---------------- kernel 8: recompute y, BN+ReLU, add x (bnfin folded in) ----------------
__global__ void out_kernel(const float* __restrict__ x, float* __restrict__ out,
                           const float* __restrict__ gamma, const float* __restrict__ beta){
    __shared__ float At[2*6*AT_RS];
    __shared__ float Us2[2304];
    __shared__ float scs[64], bis[64];
    int b  = blockIdx.y;
    int h0 = blockIdx.x * YROWS;
    int t  = threadIdx.x;           // 192
    if (t < 64){
        float n = (float)(BB*HWW);
        float mean = g_bnsum[t] / n;
        float var  = g_bnsumsq[t] / n - mean*mean;
        float sc = gamma[t] * rsqrtf(var + 1e-5f);
        scs[t] = sc;
        bis[t] = beta[t] - mean*sc;
    }
    stage_AU2(At, Us2, b, h0, t);
    __syncthreads();

    int rr = t / 48, wq = t - rr*48;
    int w0 = wq * 4;
    u64 ap[2][3][5];
    load_ap(ap, At, rr, w0);
    size_t rowoff = ((size_t)(b*64))*HWW + (size_t)(h0 + rr)*WWD + w0;
    for (int o = 0; o < 64; o++){
        float o0,o1,o2,o3;
        y_quad2(ap, Us2, o, o0, o1, o2, o3);
        float sc = scs[o], bi = bis[o];
        float4 xv = *(const float4*)&x[rowoff + (size_t)o*HWW];
        float4 r;
        r.x = xv.x + fmaxf(o0*sc + bi, 0.f);
        r.y = xv.y + fmaxf(o1*sc + bi, 0.f);
        r.z = xv.z + fmaxf(o2*sc + bi, 0.f);
        r.w = xv.w + fmaxf(o3*sc + bi, 0.f);
        *(float4*)&out[rowoff + (size_t)o*HWW] = r;
    }
}

// ---------------- launcher ----------------
extern "C" void kernel_launch(void* const* d_in, const int* in_sizes, int n_in,
                              void* d_out, int out_size){
    const float* x      = (const float*)d_in[0];
    const float* cs     = (const float*)d_in[1];
    const float* Wc     = (const float*)d_in[2];   // (7,1,3,3)
    const float* Wx     = (const float*)d_in[3];   // (512,64,3,3)
    const float* Wcs    = (const float*)d_in[4];   // (8,)
    const float* Wcv    = (const float*)d_in[5];   // (8,)
    const float* Wattn  = (const float*)d_in[6];   // (8,)
    const float* Wcomb  = (const float*)d_in[7];   // (8,)
    const float* Wsing  = (const float*)d_in[8];   // (64,64,3,3)
    const float* gamma  = (const float*)d_in[9];
    const float* beta   = (const float*)d_in[10];
    float* out = (float*)d_out;

    xconv_kernel<<<(int)((size_t)BB*CCH*HWW/8/256), 256>>>(x);
    space_kernel<<<dim3(HH, BB*NCLS), 192>>>(cs, Wc, Wcv, Wattn, Wcomb);

    int corr_smem = (XS_BASE + 2*6400) * 4;   // 102400 bytes
    cudaFuncSetAttribute(corr_tc_kernel, cudaFuncAttributeMaxDynamicSharedMemorySize, corr_smem);
    corr_tc_kernel<<<dim3(HH/RW, BB), CTHR, corr_smem>>>();

    tok2_kernel<<<64, 256>>>(Wx, Wcs);
    u_kernel<<<16, 576>>>(Wsing);
    y_kernel<<<dim3(HH/YROWS, BB), 192>>>();
    out_kernel<<<dim3(HH/YROWS, BB), 192>>>(x, out, gamma, beta);
}

// round 13
// speedup vs baseline: 1.0675x; 1.0675x over previous
#include <cuda_runtime.h>
#include <cuda_bf16.h>
#include <math.h>

#define BB   8
#define CCH  64
#define HH   192
#define WWD  192
#define HWW  (HH*WWD)
#define NCLS 2
#define NSP  8

typedef unsigned long long u64;

// packed f32x2 helpers
#define FMA2(acc, a, b)   asm("fma.rn.f32x2 %0, %1, %2, %0;" : "+l"(acc) : "l"(a), "l"(b))
#define PACK2(d, lo, hi)  asm("mov.b64 %0, {%1, %2};" : "=l"(d) : "f"(lo), "f"(hi))
#define UNPK(lo, hi, d)   asm("mov.b64 {%0, %1}, %2;" : "=f"(lo), "=f"(hi) : "l"(d))

// cp.async helpers
__device__ __forceinline__ unsigned sm_addr(const void* p){
    unsigned a; asm("{ .reg .u64 t; cvta.to.shared.u64 t, %1; cvt.u32.u64 %0, t; }" : "=r"(a) : "l"(p));
    return a;
}
__device__ __forceinline__ void cp_async16(void* smem_dst, const void* gmem_src){
    asm volatile("cp.async.cg.shared.global [%0], [%1], 16;" :: "r"(sm_addr(smem_dst)), "l"(gmem_src) : "memory");
}
#define CP_COMMIT() asm volatile("cp.async.commit_group;" ::: "memory")
#define CP_WAIT0()  asm volatile("cp.async.wait_group 0;" ::: "memory")

// ---------------- scratch (device globals; zero at module load) ----------------
__device__ __nv_bfloat16 g_sP[BB*16*194*200];
__device__ __nv_bfloat16 g_sQ[BB*16*194*200];
__device__ __nv_bfloat16 g_xbf[(size_t)BB*CCH*HWW];  // x pre-converted to bf16
__device__ float g_Apad[16*194*200];         // [bc][194][200] zero-padded attention maps
__device__ float g_R[BB*16*9*64];            // [b][sc][delta][e]
__device__ float g_S[BB*NCLS*NSP];           // per-map sums (of bf16-rounded values)
__device__ float g_tok2[BB*NCLS*CCH];        // [b][c][d]
__device__ float g_U[BB*NCLS*CCH*9];         // [b][c][o][delta]
__device__ float g_bnsum[CCH];
__device__ float g_bnsumsq[CCH];

__device__ __forceinline__ float sigmoidf_(float x){ return 1.f/(1.f+__expf(-x)); }

// ---------------- kernel 0: x -> bf16  (+ folded accumulator init) ----------------
__global__ void xconv_kernel(const float* __restrict__ x){
    if (blockIdx.x < 290){
        int i = blockIdx.x*256 + threadIdx.x;
        if (i < BB*16*9*64) g_R[i] = 0.f;
        if (i < BB*NCLS*NSP) g_S[i] = 0.f;
        if (i < BB*NCLS*CCH) g_tok2[i] = 0.f;
        if (i < CCH){ g_bnsum[i] = 0.f; g_bnsumsq[i] = 0.f; }
    }
    size_t i = ((size_t)blockIdx.x*256 + threadIdx.x)*8;
    float4 v0 = *(const float4*)&x[i];
    float4 v1 = *(const float4*)&x[i+4];
    __nv_bfloat162 p0 = __floats2bfloat162_rn(v0.x, v0.y);
    __nv_bfloat162 p1 = __floats2bfloat162_rn(v0.z, v0.w);
    __nv_bfloat162 p2 = __floats2bfloat162_rn(v1.x, v1.y);
    __nv_bfloat162 p3 = __floats2bfloat162_rn(v1.z, v1.w);
    uint4 o;
    o.x = *(unsigned*)&p0; o.y = *(unsigned*)&p1; o.z = *(unsigned*)&p2; o.w = *(unsigned*)&p3;
    *(uint4*)&g_xbf[i] = o;
}

// ---------------- kernel 1: space maps (P/Q padded layouts) + sums + attention A ----------------
__global__ void space_kernel(const float* __restrict__ cs, const float* __restrict__ Wc,
                             const float* __restrict__ Wcv, const float* __restrict__ Wattn,
                             const float* __restrict__ Wcomb){
    int h  = blockIdx.x;      // 0..191
    int bc = blockIdx.y;      // 0..15
    __shared__ float cp3[3*194];
    __shared__ float ssum[NSP];
    int t = threadIdx.x;      // 192
    if (t < NSP) ssum[t] = 0.f;
    const float* csp = cs + (size_t)bc*HWW;
    for (int idx = t; idx < 3*194; idx += 192){
        int r  = idx / 194;
        int wi = idx - r*194;
        int hh = h - 1 + r, ww = wi - 1;
        float v = 0.f;
        if (hh >= 0 && hh < HH && ww >= 0 && ww < WWD) v = sigmoidf_(csp[hh*WWD + ww]);
        cp3[idx] = v;
    }
    __syncthreads();
    int w = t;
    float cp = cp3[194 + w + 1];
    {   // attention map (full precision), padded layout
        float a = 0.f;
        #pragma unroll
        for (int s = 0; s < 8; s++) a += Wcomb[s]*Wcv[s]*sigmoidf_(cp*Wattn[s]);
        g_Apad[((size_t)bc*194 + h + 1)*200 + w + 1] = a;
    }
    float sv[8];
    sv[0] = cp;
    #pragma unroll
    for (int os = 0; os < 7; os++){
        float acc = 0.f;
        #pragma unroll
        for (int r = 0; r < 3; r++)
            #pragma unroll
            for (int c = 0; c < 3; c++)
                acc += Wc[os*9 + r*3 + c] * cp3[r*194 + w + c];
        sv[os+1] = sigmoidf_(acc);
    }
    int gr = h + 1;   // padded row index
    #pragma unroll
    for (int s = 0; s < 8; s++){
        __nv_bfloat16 bv = __float2bfloat16(sv[s]);
        size_t rowbase = ((size_t)(bc*8 + s)*194 + gr)*200;
        g_sP[rowbase + w + 1] = bv;
        g_sQ[rowbase + w]     = bv;
        float v = __bfloat162float(bv);
        #pragma unroll
        for (int off = 16; off > 0; off >>= 1) v += __shfl_down_sync(0xffffffffu, v, off);
        if ((t & 31) == 0) atomicAdd(&ssum[s], v);
    }
    __syncthreads();
    if (t < NSP) atomicAdd(&g_S[bc*NSP + t], ssum[t]);
}

// ---------------- kernel 2: correlation GEMM, bf16 m16n8k16, warp tile m32 x n48 ----------------
#define RW 6
#define CTHR 192
#define SROW_W 100      // u32 words per staged space row
#define SC_STRIDE 400   // 4 slots * SROW_W
#define SQ_OFF 6400     // word offset of Q region
#define XS_BASE 12800   // word offset of x region (2 slots * 6400)
#define XROW_W 100

__device__ __forceinline__ void stage_space_row(unsigned* sm, int b, int gr, int t){
    int slot = gr & 3;
    for (int idx = t; idx < 800; idx += CTHR){
        int j  = idx >> 1;           // 0..399
        int sc = j / 25;
        int w16 = j - sc*25;
        const __nv_bfloat16* srcA = (idx & 1) ? g_sQ : g_sP;
        unsigned* dstbase = sm + ((idx & 1) ? SQ_OFF : 0);
        const char* s = (const char*)(srcA + ((size_t)(b*16 + sc)*194 + gr)*200) + w16*16;
        unsigned* d = dstbase + sc*SC_STRIDE + slot*SROW_W + w16*4;
        cp_async16(d, s);
    }
}

__device__ __forceinline__ void stage_x_row(unsigned* sm, int b, int h, int t){
    int xslot = h & 1;
    for (int idx = t; idx < 1536; idx += CTHR){
        int e = idx / 24;
        int o = idx - e*24;
        const char* s = (const char*)(g_xbf + ((size_t)(b*64 + e))*HWW + h*WWD) + o*16;
        unsigned* d = sm + XS_BASE + xslot*6400 + e*XROW_W + o*4;
        cp_async16(d, s);
    }
}

__global__ void corr_tc_kernel(){
    extern __shared__ unsigned sm32[];
    int b  = blockIdx.y;
    int h0 = blockIdx.x * RW;
    int t  = threadIdx.x;      // 192
    int warp = t >> 5, lane = t & 31;
    int lk = lane & 3, le = lane >> 2;
    int mt2 = warp & 1;        // m-strip
    int ng  = warp >> 1;       // 0..2

    int baseoff[6], kyv[6];
    #pragma unroll
    for (int nt = 0; nt < 6; nt++){
        int n = (ng*6 + nt)*8 + le;
        int sc = n / 9, di = n - sc*9;
        int ky = di/3, kx = di - ky*3;
        int sh = 2 - kx;
        int par = sh & 1;
        baseoff[nt] = (par ? SQ_OFF : 0) + sc*SC_STRIDE + ((sh - par) >> 1) + lk;
        kyv[nt] = ky;
    }
    float acc[12][4];
    #pragma unroll
    for (int j = 0; j < 12; j++){ acc[j][0]=0.f; acc[j][1]=0.f; acc[j][2]=0.f; acc[j][3]=0.f; }

    stage_space_row(sm32, b, h0,   t);
    stage_space_row(sm32, b, h0+1, t);
    stage_space_row(sm32, b, h0+2, t);
    stage_x_row(sm32, b, h0, t);
    CP_COMMIT();

    int xrow = mt2*32 + le;
    #pragma unroll 1
    for (int rr = 0; rr < RW; rr++){
        int h = h0 + rr;
        CP_WAIT0();
        __syncthreads();
        if (rr + 1 < RW){
            stage_space_row(sm32, b, h+3, t);
            stage_x_row(sm32, b, h+1, t);
            CP_COMMIT();
        }
        int xb = XS_BASE + (h & 1)*6400 + xrow*XROW_W + lk;
        int off[6];
        #pragma unroll
        for (int nt = 0; nt < 6; nt++) off[nt] = baseoff[nt] + ((h + 2 - kyv[nt]) & 3)*SROW_W;
        #pragma unroll
        for (int ks = 0; ks < 12; ks++){
            int kw = ks*8;
            unsigned a00 = sm32[xb + kw];
            unsigned a01 = sm32[xb + 8*XROW_W  + kw];
            unsigned a02 = sm32[xb + kw + 4];
            unsigned a03 = sm32[xb + 8*XROW_W  + kw + 4];
            unsigned a10 = sm32[xb + 16*XROW_W + kw];
            unsigned a11 = sm32[xb + 24*XROW_W + kw];
            unsigned a12 = sm32[xb + 16*XROW_W + kw + 4];
            unsigned a13 = sm32[xb + 24*XROW_W + kw + 4];
            #pragma unroll
            for (int nt = 0; nt < 6; nt++){
                unsigned b0 = sm32[off[nt] + kw];
                unsigned b1 = sm32[off[nt] + kw + 4];
                asm("mma.sync.aligned.m16n8k16.row.col.f32.bf16.bf16.f32 "
                    "{%0,%1,%2,%3}, {%4,%5,%6,%7}, {%8,%9}, {%0,%1,%2,%3};"
                    : "+f"(acc[nt][0]), "+f"(acc[nt][1]), "+f"(acc[nt][2]), "+f"(acc[nt][3])
                    : "r"(a00), "r"(a01), "r"(a02), "r"(a03), "r"(b0), "r"(b1));
                asm("mma.sync.aligned.m16n8k16.row.col.f32.bf16.bf16.f32 "
                    "{%0,%1,%2,%3}, {%4,%5,%6,%7}, {%8,%9}, {%0,%1,%2,%3};"
                    : "+f"(acc[6+nt][0]), "+f"(acc[6+nt][1]), "+f"(acc[6+nt][2]), "+f"(acc[6+nt][3])
                    : "r"(a10), "r"(a11), "r"(a12), "r"(a13), "r"(b0), "r"(b1));
            }
        }
        __syncthreads();
    }
    #pragma unroll
    for (int i = 0; i < 2; i++){
        int e0 = mt2*32 + i*16 + le;
        #pragma unroll
        for (int nt = 0; nt < 6; nt++){
            int n0 = (ng*6 + nt)*8 + lk*2;
            int sc0 = n0 / 9,     di0 = n0 - sc0*9;
            int sc1 = (n0+1) / 9, di1 = (n0+1) - sc1*9;
            float* ac = acc[i*6 + nt];
            atomicAdd(&g_R[((size_t)(b*16 + sc0)*9 + di0)*64 + e0],     ac[0]);
            atomicAdd(&g_R[((size_t)(b*16 + sc1)*9 + di1)*64 + e0],     ac[1]);
            atomicAdd(&g_R[((size_t)(b*16 + sc0)*9 + di0)*64 + e0 + 8], ac[2]);
            atomicAdd(&g_R[((size_t)(b*16 + sc1)*9 + di1)*64 + e0 + 8], ac[3]);
        }
    }
}

// ---------------- kernel 3: tok2 v2 (reverted; 512 blocks, measured fastest) ----------------
__global__ void tok2_kernel(const float* __restrict__ Wx, const float* __restrict__ Wcs){
    __shared__ float wxs[576];          // reordered to [di*64+e]
    __shared__ float Rs[16*576];        // [bc][di*64+e]
    int s = blockIdx.x >> 6;
    int d = blockIdx.x & 63;
    int t = threadIdx.x;                // 256
    const float* wx = Wx + ((size_t)(s*64 + d))*576;
    for (int idx = t; idx < 576; idx += 256){
        int di = idx >> 6, e = idx & 63;
        wxs[idx] = wx[e*9 + di];
    }
    #pragma unroll
    for (int bc = 0; bc < 16; bc++){
        int bb = bc >> 1, c = bc & 1;
        const float4* s4 = (const float4*)&g_R[((size_t)(bb*16 + c*8 + s))*576];
        if (t < 144) ((float4*)&Rs[bc*576])[t] = s4[t];
    }
    __syncthreads();
    int bc = t >> 4, q = t & 15;
    const float* rr = Rs + bc*576;
    float p = 0.f;
    #pragma unroll 9
    for (int jj = 0; jj < 36; jj++){
        int k = q*36 + jj;
        p += wxs[k]*rr[k];
    }
    #pragma unroll
    for (int off = 8; off > 0; off >>= 1) p += __shfl_down_sync(0xffffffffu, p, off, 16);
    if (q == 0){
        float ws = Wcs[s] / g_S[bc*8 + s];
        atomicAdd(&g_tok2[bc*64 + d], ws*p);
    }
}

// ---------------- kernel 5: U v2 — 16 blocks = o-groups of 4, coalesced Wsingle ----------------
__global__ void u_kernel(const float* __restrict__ Wsingle){
    int og = blockIdx.x;            // o0 = og*4
    int t  = threadIdx.x;           // 576
    __shared__ float tk[16*64];
    __shared__ float ws[36*65];     // [j = ol*9+di][d], padded
    if (t < 512){
        tk[t] = g_tok2[t];
        tk[t+512] = g_tok2[t+512];
    }
    for (int idx = t; idx < 2304; idx += 576){
        int ol = idx / 576, r = idx - ol*576;   // r = d*9+di
        int d = r / 9, di = r - d*9;
        ws[(ol*9 + di)*65 + d] = Wsingle[(size_t)og*2304 + idx];
    }
    __syncthreads();
    int bc = t / 36, j = t - bc*36;
    const float* wr = ws + j*65;
    const float* tr = tk + bc*64;
    float acc = 0.f;
    #pragma unroll
    for (int d = 0; d < 64; d++) acc += wr[d]*tr[d];
    int ol = j / 9, di = j - ol*9;
    g_U[(size_t)bc*576 + (og*4 + ol)*9 + di] = acc;
}

// ---------------- shared y-compute helpers ----------------
#define YROWS 4
#define AT_RS 196
// stage A rows via cp.async from padded layout + U (duplicated pairs built after wait)
__device__ __forceinline__ void stage_AU2_async(float* At, float* Utmp, int b, int h0, int t){
    // A: 2 maps x 6 rows x 49 float4 = 588 cp16
    for (int idx = t; idx < 588; idx += 192){
        int ccv = idx / 294;
        int rem = idx - ccv*294;
        int r   = rem / 49;
        int q4  = rem - r*49;
        const float* src = &g_Apad[((size_t)(b*2 + ccv)*194 + h0 + r)*200 + q4*4];
        cp_async16(&At[ccv*(6*AT_RS) + r*AT_RS + q4*4], src);
    }
    // U: 1152 floats = 288 float4
    for (int idx = t; idx < 288; idx += 192){
        cp_async16(&Utmp[idx*4], &g_U[(size_t)b*1152 + idx*4]);
    }
    CP_COMMIT();
}

__device__ __forceinline__ void load_ap(u64 ap[2][3][5], const float* At, int rr, int w0){
    #pragma unroll
    for (int ccv = 0; ccv < 2; ccv++){
        #pragma unroll
        for (int ky = 0; ky < 3; ky++){
            const float* arow = At + ccv*(6*AT_RS) + (rr + ky)*AT_RS + w0;
            float a0=arow[0], a1=arow[1], a2=arow[2], a3=arow[3], a4=arow[4], a5=arow[5];
            PACK2(ap[ccv][ky][0], a0, a1);
            PACK2(ap[ccv][ky][1], a1, a2);
            PACK2(ap[ccv][ky][2], a2, a3);
            PACK2(ap[ccv][ky][3], a3, a4);
            PACK2(ap[ccv][ky][4], a4, a5);
        }
    }
}

__device__ __forceinline__ void y_quad2(const u64 ap[2][3][5], const float* Us2, int o,
                                        float& o0, float& o1, float& o2, float& o3){
    u64 a01 = 0ull, a23 = 0ull;
    #pragma unroll
    for (int ccv = 0; ccv < 2; ccv++){
        const u64* up = (const u64*)Us2 + (ccv*64 + o)*9;
        #pragma unroll
        for (int ky = 0; ky < 3; ky++){
            u64 u0 = up[ky*3+0], u1 = up[ky*3+1], u2 = up[ky*3+2];
            FMA2(a01, u0, ap[ccv][ky][0]);
            FMA2(a01, u1, ap[ccv][ky][1]);
            FMA2(a01, u2, ap[ccv][ky][2]);
            FMA2(a23, u0, ap[ccv][ky][2]);
            FMA2(a23, u1, ap[ccv][ky][3]);
            FMA2(a23, u2, ap[ccv][ky][4]);
        }
    }
    UNPK(o0, o1, a01);
    UNPK(o2, o3, a23);
}

// build duplicated (u,u) pairs from staged U
__device__ __forceinline__ void dup_U(float* Us2, const float* Utmp, int t){
    for (int idx = t; idx < 1152; idx += 192){
        float v = Utmp[idx];
        Us2[2*idx]   = v;
        Us2[2*idx+1] = v;
    }
}

// ---------------- kernel 6: BN stats only ----------------
__global__ void y_kernel(){
    __shared__ float At[2*6*AT_RS];
    __shared__ float Utmp[1152];
    __shared__ float Us2[2304];
    __shared__ float bs[64], bsq[64];
    int b  = blockIdx.y;
    int h0 = blockIdx.x * YROWS;
    int t  = threadIdx.x;           // 192
    if (t < 64){ bs[t] = 0.f; bsq[t] = 0.f; }
    stage_AU2_async(At, Utmp, b, h0, t);
    CP_WAIT0();
    __syncthreads();
    dup_U(Us2, Utmp, t);
    __syncthreads();

    int rr = t / 48, wq = t - rr*48;
    int w0 = wq * 4;
    u64 ap[2][3][5];
    load_ap(ap, At, rr, w0);
    for (int o = 0; o < 64; o++){
        float o0,o1,o2,o3;
        y_quad2(ap, Us2, o, o0, o1, o2, o3);
        float s1 = o0+o1+o2+o3;
        float s2 = o0*o0+o1*o1+o2*o2+o3*o3;
        #pragma unroll
        for (int off = 16; off > 0; off >>= 1){
            s1 += __shfl_down_sync(0xffffffffu, s1, off);
            s2 += __shfl_down_sync(0xffffffffu, s2, off);
        }
        if ((t & 31) == 0){ atomicAdd(&bs[o], s1); atomicAdd(&bsq[o], s2); }
    }
    __syncthreads();
    if (t < 64){ atomicAdd(&g_bnsum[t], bs[t]); atomicAdd(&g_bnsumsq[t], bsq[t]); }
}

// ---------------- kernel 8: recompute y, BN+ReLU, add x (bnfin folded in) ----------------
__global__ void out_kernel(const float* __restrict__ x, float* __restrict__ out,
                           const float* __restrict__ gamma, const float* __restrict__ beta){
    __shared__ float At[2*6*AT_RS];
    __shared__ float Utmp[1152];
    __shared__ float Us2[2304];
    __shared__ float scs[64], bis[64];
    int b  = blockIdx.y;
    int h0 = blockIdx.x * YROWS;
    int t  = threadIdx.x;           // 192
    stage_AU2_async(At, Utmp, b, h0, t);
    if (t < 64){
        float n = (float)(BB*HWW);
        float mean = g_bnsum[t] / n;
        float var  = g_bnsumsq[t] / n - mean*mean;
        float sc = gamma[t] * rsqrtf(var + 1e-5f);
        scs[t] = sc;
        bis[t] = beta[t] - mean*sc;
    }
    CP_WAIT0();
    __syncthreads();
    dup_U(Us2, Utmp, t);
    __syncthreads();

    int rr = t / 48, wq = t - rr*48;
    int w0 = wq * 4;
    u64 ap[2][3][5];
    load_ap(ap, At, rr, w0);
    size_t rowoff = ((size_t)(b*64))*HWW + (size_t)(h0 + rr)*WWD + w0;
    for (int o = 0; o < 64; o++){
        float o0,o1,o2,o3;
        y_quad2(ap, Us2, o, o0, o1, o2, o3);
        float sc = scs[o], bi = bis[o];
        float4 xv = *(const float4*)&x[rowoff + (size_t)o*HWW];
        float4 r;
        r.x = xv.x + fmaxf(o0*sc + bi, 0.f);
        r.y = xv.y + fmaxf(o1*sc + bi, 0.f);
        r.z = xv.z + fmaxf(o2*sc + bi, 0.f);
        r.w = xv.w + fmaxf(o3*sc + bi, 0.f);
        *(float4*)&out[rowoff + (size_t)o*HWW] = r;
    }
}

// ---------------- launcher ----------------
extern "C" void kernel_launch(void* const* d_in, const int* in_sizes, int n_in,
                              void* d_out, int out_size){
    const float* x      = (const float*)d_in[0];
    const float* cs     = (const float*)d_in[1];
    const float* Wc     = (const float*)d_in[2];   // (7,1,3,3)
    const float* Wx     = (const float*)d_in[3];   // (512,64,3,3)
    const float* Wcs    = (const float*)d_in[4];   // (8,)
    const float* Wcv    = (const float*)d_in[5];   // (8,)
    const float* Wattn  = (const float*)d_in[6];   // (8,)
    const float* Wcomb  = (const float*)d_in[7];   // (8,)
    const float* Wsing  = (const float*)d_in[8];   // (64,64,3,3)
    const float* gamma  = (const float*)d_in[9];
    const float* beta   = (const float*)d_in[10];
    float* out = (float*)d_out;

    xconv_kernel<<<(int)((size_t)BB*CCH*HWW/8/256), 256>>>(x);
    space_kernel<<<dim3(HH, BB*NCLS), 192>>>(cs, Wc, Wcv, Wattn, Wcomb);

    int corr_smem = (XS_BASE + 2*6400) * 4;   // 102400 bytes
    cudaFuncSetAttribute(corr_tc_kernel, cudaFuncAttributeMaxDynamicSharedMemorySize, corr_smem);
    corr_tc_kernel<<<dim3(HH/RW, BB), CTHR, corr_smem>>>();

    tok2_kernel<<<512, 256>>>(Wx, Wcs);
    u_kernel<<<16, 576>>>(Wsing);
    y_kernel<<<dim3(HH/YROWS, BB), 192>>>();
    out_kernel<<<dim3(HH/YROWS, BB), 192>>>(x, out, gamma, beta);
}